// round 4
// baseline (speedup 1.0000x reference)
#include <cuda_runtime.h>
#include <math.h>

#define BB 8
#define CC 64
#define HH 256
#define WW 256
#define THETA 0.7f

#define TILE_X 64
#define CHUNK 16
#define SIN_STRIDE 68   // padded row stride (floats) so float4 loads are 16B aligned

// Scratch (no allocations allowed in kernel_launch)
__device__ float g_pooled[BB * CC];
__device__ float g_attn[BB * CC];
__device__ float g_wpack[CC * CC * 12];   // [c][oc][12]: 9 conv taps (x THETA), edge w (x 1-THETA), 2 pad

// ---------------------------------------------------------------------------
// Kernel 0: repack weights (prescaled by THETA / 1-THETA) and zero pooled sums
// ---------------------------------------------------------------------------
__global__ void pack_weights_kernel(const float* __restrict__ Wc,
                                    const float* __restrict__ We) {
    int tid = blockIdx.x * blockDim.x + threadIdx.x;   // 4096 threads
    if (tid < BB * CC) g_pooled[tid] = 0.0f;
    if (tid >= CC * CC) return;
    int c  = tid / CC;
    int oc = tid % CC;
    float* dst = &g_wpack[(c * CC + oc) * 12];
#pragma unroll
    for (int k = 0; k < 9; k++)
        dst[k] = THETA * Wc[(oc * CC + c) * 9 + k];
    dst[9]  = (1.0f - THETA) * We[oc * CC + c];
    dst[10] = 0.0f;
    dst[11] = 0.0f;
}

// ---------------------------------------------------------------------------
// Kernel 1: fused 3x3 conv + vertical-edge 1x1 conv + combine + partial GAP
// Block: 64 output channels x 64 pixels (one row segment). 256 threads.
// Thread: 4 oc x 4 consecutive px.
// ---------------------------------------------------------------------------
__global__ void __launch_bounds__(256)
conv_kernel(const float* __restrict__ x,
            const float* __restrict__ b_conv,
            float* __restrict__ out) {
    extern __shared__ float smem[];
    float* s_in  = smem;                          // 64 ch * 3 rows * 68
    float* s_w   = smem + CC * 3 * SIN_STRIDE;    // 16 c * 64 oc * 12
    float* s_red = s_w + CHUNK * CC * 12;         // 64

    const int tid = threadIdx.x;
    const int x0  = blockIdx.x * TILE_X;
    const int y   = blockIdx.y;
    const int b   = blockIdx.z;

    // Load input tile: rows y-1..y+1, cols x0-1..x0+64, all 64 channels (zero-pad OOB)
    const float* xb = x + (size_t)b * CC * HH * WW;
    for (int idx = tid; idx < CC * 3 * 66; idx += 256) {
        int c   = idx / 198;
        int rem = idx % 198;
        int r   = rem / 66;
        int t   = rem % 66;
        int gy  = y - 1 + r;
        int gx  = x0 - 1 + t;
        float v = 0.0f;
        if ((unsigned)gy < HH && (unsigned)gx < WW)
            v = xb[(c * HH + gy) * WW + gx];
        s_in[(c * 3 + r) * SIN_STRIDE + t] = v;
    }
    if (tid < CC) s_red[tid] = 0.0f;

    const int px_thr = tid & 15;    // warp covers 16 px groups x 2 oc groups
    const int oc_thr = tid >> 4;
    const int pxbase = px_thr * 4;
    const int ocbase = oc_thr * 4;

    float acc[4][4];
#pragma unroll
    for (int i = 0; i < 4; i++) {
        float bias = THETA * __ldg(&b_conv[ocbase + i]);
#pragma unroll
        for (int j = 0; j < 4; j++) acc[i][j] = bias;
    }

    const float4* wsrc = (const float4*)g_wpack;
    float4* s_w4 = (float4*)s_w;

    for (int chunk = 0; chunk < CC / CHUNK; chunk++) {
        __syncthreads();
        // stage 16-input-channel weight chunk (coalesced float4 copies)
        for (int idx = tid; idx < CHUNK * CC * 3; idx += 256)
            s_w4[idx] = wsrc[chunk * (CHUNK * CC * 3) + idx];
        __syncthreads();

#pragma unroll 2
        for (int cl = 0; cl < CHUNK; cl++) {
            const int c = chunk * CHUNK + cl;
            const float* row = &s_in[c * 3 * SIN_STRIDE + pxbase];

            float r0[6], r1[6], r2[6];
            {
                float4 a0 = *(const float4*)(row);
                float2 a1 = *(const float2*)(row + 4);
                r0[0]=a0.x; r0[1]=a0.y; r0[2]=a0.z; r0[3]=a0.w; r0[4]=a1.x; r0[5]=a1.y;
                float4 b0 = *(const float4*)(row + SIN_STRIDE);
                float2 b1 = *(const float2*)(row + SIN_STRIDE + 4);
                r1[0]=b0.x; r1[1]=b0.y; r1[2]=b0.z; r1[3]=b0.w; r1[4]=b1.x; r1[5]=b1.y;
                float4 c0 = *(const float4*)(row + 2 * SIN_STRIDE);
                float2 c1 = *(const float2*)(row + 2 * SIN_STRIDE + 4);
                r2[0]=c0.x; r2[1]=c0.y; r2[2]=c0.z; r2[3]=c0.w; r2[4]=c1.x; r2[5]=c1.y;
            }

            float dv[4];
#pragma unroll
            for (int j = 0; j < 4; j++)
                dv[j] = fabsf(r0[j + 1] - r2[j + 1]);

#pragma unroll
            for (int i = 0; i < 4; i++) {
                const float* wp = &s_w[(cl * CC + ocbase + i) * 12];
                float4 wa = *(const float4*)(wp);
                float4 wb = *(const float4*)(wp + 4);
                float4 wc = *(const float4*)(wp + 8);
#pragma unroll
                for (int j = 0; j < 4; j++) {
                    acc[i][j] += wa.x * r0[j]     + wa.y * r0[j + 1] + wa.z * r0[j + 2]
                               + wa.w * r1[j]     + wb.x * r1[j + 1] + wb.y * r1[j + 2]
                               + wb.z * r2[j]     + wb.w * r2[j + 1] + wc.x * r2[j + 2]
                               + wc.y * dv[j];
                }
            }
        }
    }

    // Write combined (float4, coalesced) + block-level GAP partials
#pragma unroll
    for (int i = 0; i < 4; i++) {
        const int oc = ocbase + i;
        float4 v = make_float4(acc[i][0], acc[i][1], acc[i][2], acc[i][3]);
        *(float4*)&out[(((size_t)b * CC + oc) * HH + y) * WW + x0 + pxbase] = v;
        atomicAdd(&s_red[oc], acc[i][0] + acc[i][1] + acc[i][2] + acc[i][3]);
    }
    __syncthreads();
    if (tid < CC) atomicAdd(&g_pooled[b * CC + tid], s_red[tid]);
}

// ---------------------------------------------------------------------------
// Kernel 2: SE attention (GAP -> 1x1 -> ReLU -> 1x1 -> sigmoid), 1 block
// ---------------------------------------------------------------------------
__global__ void attn_kernel(const float* __restrict__ W1, const float* __restrict__ b1,
                            const float* __restrict__ W2, const float* __restrict__ b2) {
    __shared__ float sh[BB * 8];
    const int t = threadIdx.x;
    if (t < BB * 8) {
        int b = t >> 3, r = t & 7;
        float s = b1[r];
        const float inv = 1.0f / (float)(HH * WW);
#pragma unroll
        for (int c = 0; c < CC; c++)
            s += (g_pooled[b * CC + c] * inv) * W1[r * CC + c];
        sh[t] = fmaxf(s, 0.0f);
    }
    __syncthreads();
    for (int idx = t; idx < BB * CC; idx += 256) {
        int b = idx >> 6, o = idx & 63;
        float s = b2[o];
#pragma unroll
        for (int r = 0; r < 8; r++)
            s += sh[b * 8 + r] * W2[o * 8 + r];
        g_attn[idx] = 1.0f / (1.0f + expf(-s));
    }
}

// ---------------------------------------------------------------------------
// Kernel 3: scale output by per-(b,c) attention (float4 grid)
// ---------------------------------------------------------------------------
__global__ void scale_kernel(float* __restrict__ out) {
    int i = blockIdx.x * blockDim.x + threadIdx.x;   // exactly B*C*H*W/4 threads
    float4 v = ((float4*)out)[i];
    float a = g_attn[i >> 14];                       // 65536/4 float4 per (b,c)
    v.x *= a; v.y *= a; v.z *= a; v.w *= a;
    ((float4*)out)[i] = v;
}

// ---------------------------------------------------------------------------
extern "C" void kernel_launch(void* const* d_in, const int* in_sizes, int n_in,
                              void* d_out, int out_size) {
    const float* x  = (const float*)d_in[0];
    const float* Wc = (const float*)d_in[1];
    const float* bc = (const float*)d_in[2];
    const float* We = (const float*)d_in[3];
    const float* W1 = (const float*)d_in[4];
    const float* b1 = (const float*)d_in[5];
    const float* W2 = (const float*)d_in[6];
    const float* b2 = (const float*)d_in[7];
    float* out = (float*)d_out;

    const int smem_bytes = (CC * 3 * SIN_STRIDE + CHUNK * CC * 12 + CC) * 4;  // 101632
    cudaFuncSetAttribute(conv_kernel, cudaFuncAttributeMaxDynamicSharedMemorySize, smem_bytes);

    pack_weights_kernel<<<16, 256>>>(Wc, We);

    dim3 grid(WW / TILE_X, HH, BB);
    conv_kernel<<<grid, 256, smem_bytes>>>(x, bc, out);

    attn_kernel<<<1, 256>>>(W1, b1, W2, b2);

    scale_kernel<<<(BB * CC * HH * WW / 4) / 256, 256>>>(out);
}

// round 5
// speedup vs baseline: 1.0102x; 1.0102x over previous
#include <cuda_runtime.h>
#include <math.h>

#define BB 8
#define CC 64
#define HH 256
#define WW 256
#define THETA 0.7f

#define TILE_X 64
#define CHUNK 8          // input channels per weight-staging chunk
#define SIN_STRIDE 68    // padded row stride (floats); 68 % 4 == 0 -> float4 aligned

typedef unsigned long long u64;

// Scratch (no allocations allowed in kernel_launch)
__device__ float g_pooled[BB * CC];
__device__ float g_attn[BB * CC];
// Packed duplicated weights: [c][oc][10 taps] as float2 (w,w).
// taps 0..8 = 3x3 conv (row-major, prescaled by THETA), tap 9 = edge weight (prescaled by 1-THETA)
__device__ float2 g_wpack2[CC * CC * 10];

// ---------------- f32x2 helpers ----------------
__device__ __forceinline__ u64 pk2(float lo, float hi) {
    u64 r;
    asm("mov.b64 %0, {%1, %2};" : "=l"(r) : "r"(__float_as_uint(lo)), "r"(__float_as_uint(hi)));
    return r;
}
__device__ __forceinline__ u64 fma2(u64 a, u64 b, u64 c) {
    u64 d;
    asm("fma.rn.f32x2 %0, %1, %2, %3;" : "=l"(d) : "l"(a), "l"(b), "l"(c));
    return d;
}
__device__ __forceinline__ void upk2(u64 v, float& lo, float& hi) {
    unsigned int l, h;
    asm("mov.b64 {%0, %1}, %2;" : "=r"(l), "=r"(h) : "l"(v));
    lo = __uint_as_float(l);
    hi = __uint_as_float(h);
}
#define NEG1X2 0xBF800000BF800000ULL
#define ABSMASK 0x7FFFFFFF7FFFFFFFULL

// ---------------------------------------------------------------------------
// Kernel 0: repack weights (prescaled, duplicated into f32x2 pairs), zero GAP
// ---------------------------------------------------------------------------
__global__ void pack_weights_kernel(const float* __restrict__ Wc,
                                    const float* __restrict__ We) {
    int tid = blockIdx.x * blockDim.x + threadIdx.x;   // 4096 threads
    if (tid < BB * CC) g_pooled[tid] = 0.0f;
    if (tid >= CC * CC) return;
    int c  = tid / CC;
    int oc = tid % CC;
    float2* dst = &g_wpack2[(c * CC + oc) * 10];
#pragma unroll
    for (int k = 0; k < 9; k++) {
        float w = THETA * Wc[(oc * CC + c) * 9 + k];
        dst[k] = make_float2(w, w);
    }
    float we = (1.0f - THETA) * We[oc * CC + c];
    dst[9] = make_float2(we, we);
}

// ---------------------------------------------------------------------------
// Kernel 1: fused 3x3 conv + |vertical diff| 1x1 conv + combine + partial GAP
// Block: 64 oc x (2 rows x 64 px). 256 threads. Thread: 4 oc x 2 rows x 4 px,
// computed as packed f32x2 pixel-pairs (fma.rn.f32x2 = 2 FMA/lane).
// ---------------------------------------------------------------------------
__global__ void __launch_bounds__(256, 2)
conv_kernel(const float* __restrict__ x,
            const float* __restrict__ b_conv,
            float* __restrict__ out) {
    extern __shared__ float smem[];
    float* s_in  = smem;                               // 64 ch * 4 rows * 68
    u64*   s_w   = (u64*)(smem + CC * 4 * SIN_STRIDE); // CHUNK c * 64 oc * 10 (dup pairs)
    float* s_red = (float*)(s_w + CHUNK * CC * 10);    // 64

    const int tid = threadIdx.x;
    const int x0  = blockIdx.x * TILE_X;
    const int y0  = blockIdx.y * 2;        // two output rows: y0, y0+1
    const int b   = blockIdx.z;

    // Stage input tile: rows y0-1 .. y0+2, cols x0-1 .. x0+64, all 64 ch (zero-pad)
    const float* xb = x + (size_t)b * CC * HH * WW;
    for (int idx = tid; idx < CC * 4 * 66; idx += 256) {
        int c   = idx / 264;
        int rem = idx % 264;
        int r   = rem / 66;
        int t   = rem % 66;
        int gy  = y0 - 1 + r;
        int gx  = x0 - 1 + t;
        float v = 0.0f;
        if ((unsigned)gy < HH && (unsigned)gx < WW)
            v = xb[(c * HH + gy) * WW + gx];
        s_in[(c * 4 + r) * SIN_STRIDE + t] = v;
    }
    if (tid < CC) s_red[tid] = 0.0f;

    const int px_thr = tid & 15;     // 16 px-groups of 4 px
    const int oc_thr = tid >> 4;     // 16 oc-groups of 4 oc
    const int pxbase = px_thr * 4;
    const int ocbase = oc_thr * 4;

    // acc[oc][row A/B][px-pair], packed f32x2
    u64 acc[4][2][2];
#pragma unroll
    for (int i = 0; i < 4; i++) {
        float bias = THETA * __ldg(&b_conv[ocbase + i]);
        u64 bp = pk2(bias, bias);
        acc[i][0][0] = bp; acc[i][0][1] = bp;
        acc[i][1][0] = bp; acc[i][1][1] = bp;
    }

    const float4* wsrc_all = (const float4*)g_wpack2;   // 5 float4 per (c,oc)
    float4* s_w4 = (float4*)s_w;

    for (int chunk = 0; chunk < CC / CHUNK; chunk++) {
        __syncthreads();
        // stage dup-weight chunk (coalesced float4): CHUNK*64*5 float4
        for (int idx = tid; idx < CHUNK * CC * 5; idx += 256)
            s_w4[idx] = wsrc_all[chunk * (CHUNK * CC * 5) + idx];
        __syncthreads();

#pragma unroll 1
        for (int cl = 0; cl < CHUNK; cl++) {
            const int c = chunk * CHUNK + cl;
            const float* rowp = &s_in[(c * 4) * SIN_STRIDE + pxbase];

            // Load 4 input rows, 6 floats each
            float r[4][6];
#pragma unroll
            for (int rr = 0; rr < 4; rr++) {
                float4 a = *(const float4*)(rowp + rr * SIN_STRIDE);
                float2 bq = *(const float2*)(rowp + rr * SIN_STRIDE + 4);
                r[rr][0] = a.x; r[rr][1] = a.y; r[rr][2] = a.z;
                r[rr][3] = a.w; r[rr][4] = bq.x; r[rr][5] = bq.y;
            }
            // Sliding pixel-pairs p[row][s] = (r[s], r[s+1])
            u64 p[4][5];
#pragma unroll
            for (int rr = 0; rr < 4; rr++) {
                p[rr][0] = pk2(r[rr][0], r[rr][1]);
                p[rr][1] = pk2(r[rr][1], r[rr][2]);
                p[rr][2] = pk2(r[rr][2], r[rr][3]);
                p[rr][3] = pk2(r[rr][3], r[rr][4]);
                p[rr][4] = pk2(r[rr][4], r[rr][5]);
            }
            // |vertical diff| packed: row A uses local rows 0,2; row B uses 1,3
            u64 dA0 = fma2(p[2][1], NEG1X2, p[0][1]) & ABSMASK;  // cols (1,2)
            u64 dA1 = fma2(p[2][3], NEG1X2, p[0][3]) & ABSMASK;  // cols (3,4)
            u64 dB0 = fma2(p[3][1], NEG1X2, p[1][1]) & ABSMASK;
            u64 dB1 = fma2(p[3][3], NEG1X2, p[1][3]) & ABSMASK;

#pragma unroll
            for (int i = 0; i < 4; i++) {
                const ulonglong2* wp =
                    (const ulonglong2*)&s_w[(cl * CC + ocbase + i) * 10];
                ulonglong2 w01 = wp[0];   // taps 0,1
                ulonglong2 w23 = wp[1];   // taps 2,3
                ulonglong2 w45 = wp[2];   // taps 4,5
                ulonglong2 w67 = wp[3];   // taps 6,7
                ulonglong2 w89 = wp[4];   // tap 8, edge

                // tap k = kr*3+kc : rowA operand p[kr][kc+2*jp], rowB p[kr+1][kc+2*jp]
                acc[i][0][0] = fma2(w01.x, p[0][0], acc[i][0][0]);
                acc[i][0][1] = fma2(w01.x, p[0][2], acc[i][0][1]);
                acc[i][1][0] = fma2(w01.x, p[1][0], acc[i][1][0]);
                acc[i][1][1] = fma2(w01.x, p[1][2], acc[i][1][1]);

                acc[i][0][0] = fma2(w01.y, p[0][1], acc[i][0][0]);
                acc[i][0][1] = fma2(w01.y, p[0][3], acc[i][0][1]);
                acc[i][1][0] = fma2(w01.y, p[1][1], acc[i][1][0]);
                acc[i][1][1] = fma2(w01.y, p[1][3], acc[i][1][1]);

                acc[i][0][0] = fma2(w23.x, p[0][2], acc[i][0][0]);
                acc[i][0][1] = fma2(w23.x, p[0][4], acc[i][0][1]);
                acc[i][1][0] = fma2(w23.x, p[1][2], acc[i][1][0]);
                acc[i][1][1] = fma2(w23.x, p[1][4], acc[i][1][1]);

                acc[i][0][0] = fma2(w23.y, p[1][0], acc[i][0][0]);
                acc[i][0][1] = fma2(w23.y, p[1][2], acc[i][0][1]);
                acc[i][1][0] = fma2(w23.y, p[2][0], acc[i][1][0]);
                acc[i][1][1] = fma2(w23.y, p[2][2], acc[i][1][1]);

                acc[i][0][0] = fma2(w45.x, p[1][1], acc[i][0][0]);
                acc[i][0][1] = fma2(w45.x, p[1][3], acc[i][0][1]);
                acc[i][1][0] = fma2(w45.x, p[2][1], acc[i][1][0]);
                acc[i][1][1] = fma2(w45.x, p[2][3], acc[i][1][1]);

                acc[i][0][0] = fma2(w45.y, p[1][2], acc[i][0][0]);
                acc[i][0][1] = fma2(w45.y, p[1][4], acc[i][0][1]);
                acc[i][1][0] = fma2(w45.y, p[2][2], acc[i][1][0]);
                acc[i][1][1] = fma2(w45.y, p[2][4], acc[i][1][1]);

                acc[i][0][0] = fma2(w67.x, p[2][0], acc[i][0][0]);
                acc[i][0][1] = fma2(w67.x, p[2][2], acc[i][0][1]);
                acc[i][1][0] = fma2(w67.x, p[3][0], acc[i][1][0]);
                acc[i][1][1] = fma2(w67.x, p[3][2], acc[i][1][1]);

                acc[i][0][0] = fma2(w67.y, p[2][1], acc[i][0][0]);
                acc[i][0][1] = fma2(w67.y, p[2][3], acc[i][0][1]);
                acc[i][1][0] = fma2(w67.y, p[3][1], acc[i][1][0]);
                acc[i][1][1] = fma2(w67.y, p[3][3], acc[i][1][1]);

                acc[i][0][0] = fma2(w89.x, p[2][2], acc[i][0][0]);
                acc[i][0][1] = fma2(w89.x, p[2][4], acc[i][0][1]);
                acc[i][1][0] = fma2(w89.x, p[3][2], acc[i][1][0]);
                acc[i][1][1] = fma2(w89.x, p[3][4], acc[i][1][1]);

                acc[i][0][0] = fma2(w89.y, dA0, acc[i][0][0]);
                acc[i][0][1] = fma2(w89.y, dA1, acc[i][0][1]);
                acc[i][1][0] = fma2(w89.y, dB0, acc[i][1][0]);
                acc[i][1][1] = fma2(w89.y, dB1, acc[i][1][1]);
            }
        }
    }

    // Unpack, store (float4 coalesced), and accumulate GAP partials
#pragma unroll
    for (int i = 0; i < 4; i++) {
        const int oc = ocbase + i;
        float sum = 0.0f;
#pragma unroll
        for (int rsel = 0; rsel < 2; rsel++) {
            float4 v;
            upk2(acc[i][rsel][0], v.x, v.y);
            upk2(acc[i][rsel][1], v.z, v.w);
            *(float4*)&out[(((size_t)b * CC + oc) * HH + (y0 + rsel)) * WW + x0 + pxbase] = v;
            sum += v.x + v.y + v.z + v.w;
        }
        atomicAdd(&s_red[oc], sum);
    }
    __syncthreads();
    if (tid < CC) atomicAdd(&g_pooled[b * CC + tid], s_red[tid]);
}

// ---------------------------------------------------------------------------
// Kernel 2: SE attention (GAP -> 1x1 -> ReLU -> 1x1 -> sigmoid), 1 block
// ---------------------------------------------------------------------------
__global__ void attn_kernel(const float* __restrict__ W1, const float* __restrict__ b1,
                            const float* __restrict__ W2, const float* __restrict__ b2) {
    __shared__ float sh[BB * 8];
    const int t = threadIdx.x;
    if (t < BB * 8) {
        int b = t >> 3, r = t & 7;
        float s = b1[r];
        const float inv = 1.0f / (float)(HH * WW);
#pragma unroll
        for (int c = 0; c < CC; c++)
            s += (g_pooled[b * CC + c] * inv) * W1[r * CC + c];
        sh[t] = fmaxf(s, 0.0f);
    }
    __syncthreads();
    for (int idx = t; idx < BB * CC; idx += 256) {
        int b = idx >> 6, o = idx & 63;
        float s = b2[o];
#pragma unroll
        for (int r = 0; r < 8; r++)
            s += sh[b * 8 + r] * W2[o * 8 + r];
        g_attn[idx] = 1.0f / (1.0f + expf(-s));
    }
}

// ---------------------------------------------------------------------------
// Kernel 3: scale output by per-(b,c) attention (float4 grid)
// ---------------------------------------------------------------------------
__global__ void scale_kernel(float* __restrict__ out) {
    int i = blockIdx.x * blockDim.x + threadIdx.x;   // exactly B*C*H*W/4 threads
    float4 v = ((float4*)out)[i];
    float a = g_attn[i >> 14];                       // 65536/4 float4 per (b,c)
    v.x *= a; v.y *= a; v.z *= a; v.w *= a;
    ((float4*)out)[i] = v;
}

// ---------------------------------------------------------------------------
extern "C" void kernel_launch(void* const* d_in, const int* in_sizes, int n_in,
                              void* d_out, int out_size) {
    const float* x  = (const float*)d_in[0];
    const float* Wc = (const float*)d_in[1];
    const float* bc = (const float*)d_in[2];
    const float* We = (const float*)d_in[3];
    const float* W1 = (const float*)d_in[4];
    const float* b1 = (const float*)d_in[5];
    const float* W2 = (const float*)d_in[6];
    const float* b2 = (const float*)d_in[7];
    float* out = (float*)d_out;

    // 69632 (input) + 40960 (dup weights) + 256 (reduction) = 110848 bytes
    const int smem_bytes = CC * 4 * SIN_STRIDE * 4 + CHUNK * CC * 10 * 8 + CC * 4;
    cudaFuncSetAttribute(conv_kernel, cudaFuncAttributeMaxDynamicSharedMemorySize, smem_bytes);

    pack_weights_kernel<<<16, 256>>>(Wc, We);

    dim3 grid(WW / TILE_X, HH / 2, BB);
    conv_kernel<<<grid, 256, smem_bytes>>>(x, bc, out);

    attn_kernel<<<1, 256>>>(W1, b1, W2, b2);

    scale_kernel<<<(BB * CC * HH * WW / 4) / 256, 256>>>(out);
}